// round 5
// baseline (speedup 1.0000x reference)
#include <cuda_runtime.h>
#include <cuda_bf16.h>
#include <math.h>

#define NNODES 100000
#define NEDGES 1600000
#define DHID 128
#define DOUT 64
#define BN_EPS 1e-5f
#define NB ((NNODES + 255) / 256)   // 391 blocks for scan

// buffer selectors
#define SEL_ARG 0
#define SEL_AGG 1
#define SEL_PRE 2

// ---------------- scratch (static device globals; no allocation) -------------
__device__ __align__(16) float g_agg[NNODES * DHID];
__device__ __align__(16) float g_pre[NNODES * DHID];
__device__ int   g_rowptr[NNODES + 1];
__device__ int   g_cursor[NNODES];
__device__ int   g_bsum[NB];
__device__ int   g_boff[NB];
__device__ int   g_srcs[NEDGES];
__device__ __align__(16) float g_wts [NEDGES];
__device__ float g_stats[2 * DHID];
__device__ __align__(16) float g_scale[DHID];
__device__ __align__(16) float g_shift[DHID];
__device__ int   g_is64;

__device__ __forceinline__ const float* sel_cbuf(int sel, const float* arg) {
    switch (sel) {
        case SEL_AGG: return g_agg;
        case SEL_PRE: return g_pre;
        default:      return arg;
    }
}
__device__ __forceinline__ float* sel_mbuf(int sel, float* arg) {
    switch (sel) {
        case SEL_AGG: return g_agg;
        case SEL_PRE: return g_pre;
        default:      return arg;
    }
}

// f32x2 packed-FMA helpers (FFMA2 — PTX-only path, full-rate fp32)
__device__ __forceinline__ void fma2(unsigned long long& d,
                                     unsigned long long a,
                                     unsigned long long b) {
    asm("fma.rn.f32x2 %0, %1, %2, %0;" : "+l"(d) : "l"(a), "l"(b));
}
__device__ __forceinline__ unsigned long long dup2(float v) {
    unsigned long long r; unsigned u = __float_as_uint(v);
    asm("mov.b64 %0, {%1, %1};" : "=l"(r) : "r"(u));
    return r;
}
__device__ __forceinline__ float2 unpack2(unsigned long long v) {
    unsigned lo, hi;
    asm("mov.b64 {%0, %1}, %2;" : "=r"(lo), "=r"(hi) : "l"(v));
    return make_float2(__uint_as_float(lo), __uint_as_float(hi));
}

// edge index fetch honoring runtime dtype flag (int32 vs int64 words)
__device__ __forceinline__ int fetch_src(const int* ei32, int e, int is64) {
    return is64 ? ei32[2 * e] : ei32[e];
}
__device__ __forceinline__ int fetch_dst(const int* ei32, int e, int is64) {
    return is64 ? ei32[2 * (NEDGES + e)] : ei32[NEDGES + e];
}

// ---------------- dtype detection --------------------------------------------
__global__ void detect_dtype_kernel(const int* __restrict__ ei32) {
    __shared__ int s_nonzero;
    if (threadIdx.x == 0) s_nonzero = 0;
    __syncthreads();
    for (int k = threadIdx.x; k < 4096; k += blockDim.x) {
        if (ei32[2 * k + 1] != 0) atomicOr(&s_nonzero, 1);
    }
    __syncthreads();
    if (threadIdx.x == 0) g_is64 = s_nonzero ? 0 : 1;
}

// ---------------- small utility kernels --------------------------------------
__global__ void zero_cursor_kernel() {
    int i = blockIdx.x * blockDim.x + threadIdx.x;
    if (i < NNODES) g_cursor[i] = 0;
}
__global__ void zero_stats_kernel() {
    int i = threadIdx.x;
    if (i < 2 * DHID) g_stats[i] = 0.0f;
}

// ---------------- CSR build ---------------------------------------------------
__global__ void hist_kernel(const int* __restrict__ ei32) {
    int e = blockIdx.x * blockDim.x + threadIdx.x;
    if (e < NEDGES) {
        int d = fetch_dst(ei32, e, g_is64);
        atomicAdd(&g_cursor[d], 1);
    }
}

// parallel scan stage 1: per-block sums of counts
__global__ void block_reduce_kernel() {
    __shared__ int ws[8];
    int tid = threadIdx.x, lane = tid & 31, wid = tid >> 5;
    int i = blockIdx.x * 256 + tid;
    int v = (i < NNODES) ? g_cursor[i] : 0;
    #pragma unroll
    for (int d = 16; d > 0; d >>= 1) v += __shfl_down_sync(0xFFFFFFFFu, v, d);
    if (lane == 0) ws[wid] = v;
    __syncthreads();
    if (wid == 0) {
        int s = (lane < 8) ? ws[lane] : 0;
        #pragma unroll
        for (int d = 4; d > 0; d >>= 1) s += __shfl_down_sync(0xFFFFFFFFu, s, d);
        if (lane == 0) g_bsum[blockIdx.x] = s;
    }
}

// stage 2: exclusive scan of NB block sums (single block, 512 threads)
__global__ void scan_bsums_kernel() {
    __shared__ int wsum[16];
    int tid = threadIdx.x, lane = tid & 31, wid = tid >> 5;
    int v = (tid < NB) ? g_bsum[tid] : 0;
    int x = v;
    #pragma unroll
    for (int d = 1; d < 32; d <<= 1) {
        int y = __shfl_up_sync(0xFFFFFFFFu, x, d);
        if (lane >= d) x += y;
    }
    if (lane == 31) wsum[wid] = x;
    __syncthreads();
    if (wid == 0) {
        int s = (lane < 16) ? wsum[lane] : 0;
        #pragma unroll
        for (int d = 1; d < 16; d <<= 1) {
            int y = __shfl_up_sync(0xFFFFFFFFu, s, d);
            if (lane >= d) s += y;
        }
        if (lane < 16) wsum[lane] = s;
    }
    __syncthreads();
    int incl = x + (wid > 0 ? wsum[wid - 1] : 0);
    if (tid < NB) g_boff[tid] = incl - v;
    if (tid == NB - 1) g_rowptr[NNODES] = incl;
}

// stage 3: intra-block exclusive scan + block offset -> rowptr + cursor
__global__ void block_scan_kernel() {
    __shared__ int ws[8];
    int tid = threadIdx.x, lane = tid & 31, wid = tid >> 5;
    int i = blockIdx.x * 256 + tid;
    int v = (i < NNODES) ? g_cursor[i] : 0;
    int x = v;
    #pragma unroll
    for (int d = 1; d < 32; d <<= 1) {
        int y = __shfl_up_sync(0xFFFFFFFFu, x, d);
        if (lane >= d) x += y;
    }
    if (lane == 31) ws[wid] = x;
    __syncthreads();
    if (wid == 0 && lane < 8) {
        int s = ws[lane];
        #pragma unroll
        for (int d = 1; d < 8; d <<= 1) {
            int y = __shfl_up_sync(0x000000FFu, s, d);
            if (lane >= d) s += y;
        }
        ws[lane] = s;
    }
    __syncthreads();
    int excl = x - v + (wid > 0 ? ws[wid - 1] : 0) + g_boff[blockIdx.x];
    if (i < NNODES) { g_rowptr[i] = excl; g_cursor[i] = excl; }
}

__global__ void scatter_kernel(const int* __restrict__ ei32,
                               const float* __restrict__ ew) {
    int e = blockIdx.x * blockDim.x + threadIdx.x;
    if (e < NEDGES) {
        int is64 = g_is64;
        int s = fetch_src(ei32, e, is64);
        int d = fetch_dst(ei32, e, is64);
        float w = ew[e];
        int pos = atomicAdd(&g_cursor[d], 1);
        g_srcs[pos] = s;
        g_wts [pos] = w;
    }
}

// ---------------- propagate: warp-per-node CSR gather-reduce -> g_agg ---------
// BN=true: source is g_pre with scale/shift/relu applied on the fly.
template <bool BN>
__global__ void propagate_kernel(int hsel, const float* __restrict__ harg) {
    const float* __restrict__ h = BN ? g_pre : sel_cbuf(hsel, harg);
    int warp = (blockIdx.x * blockDim.x + threadIdx.x) >> 5;
    int lane = threadIdx.x & 31;
    if (warp >= NNODES) return;
    float4 sc, sh;
    if (BN) {
        sc = ((const float4*)g_scale)[lane];
        sh = ((const float4*)g_shift)[lane];
    }
    int beg = g_rowptr[warp];
    int end = g_rowptr[warp + 1];
    float4 acc = make_float4(0.f, 0.f, 0.f, 0.f);
    for (int e = beg; e < end; e++) {
        int   s = g_srcs[e];
        float w = g_wts[e];
        float4 v = *((const float4*)(h + (size_t)s * DHID) + lane);
        if (BN) {
            v.x = fmaxf(v.x * sc.x + sh.x, 0.f);
            v.y = fmaxf(v.y * sc.y + sh.y, 0.f);
            v.z = fmaxf(v.z * sc.z + sh.z, 0.f);
            v.w = fmaxf(v.w * sc.w + sh.w, 0.f);
        }
        acc.x += w * v.x; acc.y += w * v.y;
        acc.z += w * v.z; acc.w += w * v.w;
    }
    ((float4*)(g_agg + (size_t)warp * DHID))[lane] = acc;
}

// ---------------- GEMM: C[N,NC] = A[N,128] @ W[NC,128]^T + bias ---------------
// 128xNC block tile, 256 threads, 8-row x 8-col per thread, f32x2 FMA.
// W transposed into smem during staging (no separate transpose kernel).
template <int NC, bool RELU>
__launch_bounds__(256, 2)
__global__ void gemm_kernel(int asel, const float* __restrict__ Aarg,
                            const float* __restrict__ W,
                            const float* __restrict__ bias,
                            int csel, float* __restrict__ Carg) {
    constexpr int K = 128, BK = 32, BM = 128;
    constexpr int TCX = NC / 8;          // thread cols
    constexpr int TCY = 256 / TCX;       // thread rows
    constexpr int TMR = BM / TCY;        // rows per thread (8 or 4)
    __shared__ float As[BK][BM];
    __shared__ float Ws[BK][NC];

    const float* __restrict__ A = sel_cbuf(asel, Aarg);
    float* __restrict__ C = sel_mbuf(csel, Carg);

    int tid  = threadIdx.x;
    int tc   = tid % TCX;
    int tr   = tid / TCX;
    int row0 = blockIdx.x * BM;

    unsigned long long acc2[TMR / 2][8];
    #pragma unroll
    for (int m = 0; m < TMR / 2; m++)
        #pragma unroll
        for (int n = 0; n < 8; n++) acc2[m][n] = 0ull;

    for (int k0 = 0; k0 < K; k0 += BK) {
        // stage A: As[kk][r] = A[row0+r][k0+kk]
        {
            int r  = tid & 127;
            int kb0 = (tid >> 7) * 4;            // 0 or 4
            int gr = row0 + r;
            #pragma unroll
            for (int it = 0; it < 4; it++) {
                int kb = it * 8 + kb0;
                float4 v = (gr < NNODES)
                    ? *(const float4*)(A + (size_t)gr * K + k0 + kb)
                    : make_float4(0.f, 0.f, 0.f, 0.f);
                As[kb + 0][r] = v.x; As[kb + 1][r] = v.y;
                As[kb + 2][r] = v.z; As[kb + 3][r] = v.w;
            }
        }
        // stage W transposed: Ws[kk][c] = W[c][k0+kk]
        {
            constexpr int GK = (256 / NC) * 4;   // k-span per iter: 8 or 16
            int c  = tid % NC;
            int kb0 = (tid / NC) * 4;
            #pragma unroll
            for (int it = 0; it < BK / GK; it++) {
                int kb = it * GK + kb0;
                float4 v = *(const float4*)(W + (size_t)c * K + k0 + kb);
                Ws[kb + 0][c] = v.x; Ws[kb + 1][c] = v.y;
                Ws[kb + 2][c] = v.z; Ws[kb + 3][c] = v.w;
            }
        }
        __syncthreads();

        #pragma unroll
        for (int kk = 0; kk < BK; kk++) {
            unsigned long long ap[TMR / 2];
            const ulonglong2* apt = (const ulonglong2*)&As[kk][tr * TMR];
            #pragma unroll
            for (int q = 0; q < TMR / 4; q++) {
                ulonglong2 t = apt[q];
                ap[2 * q] = t.x; ap[2 * q + 1] = t.y;
            }
            float wv[8];
            *(float4*)&wv[0] = *(const float4*)&Ws[kk][tc * 8];
            *(float4*)&wv[4] = *(const float4*)&Ws[kk][tc * 8 + 4];
            unsigned long long bd[8];
            #pragma unroll
            for (int n = 0; n < 8; n++) bd[n] = dup2(wv[n]);
            #pragma unroll
            for (int m = 0; m < TMR / 2; m++)
                #pragma unroll
                for (int n = 0; n < 8; n++)
                    fma2(acc2[m][n], ap[m], bd[n]);
        }
        __syncthreads();
    }

    // epilogue: bias (+relu), store
    float bb[8];
    *(float4*)&bb[0] = *(const float4*)(bias + tc * 8);
    *(float4*)&bb[4] = *(const float4*)(bias + tc * 8 + 4);
    #pragma unroll
    for (int m = 0; m < TMR / 2; m++) {
        float lo[8], hi[8];
        #pragma unroll
        for (int n = 0; n < 8; n++) {
            float2 p = unpack2(acc2[m][n]);
            lo[n] = p.x; hi[n] = p.y;
        }
        #pragma unroll
        for (int hh = 0; hh < 2; hh++) {
            int r = row0 + tr * TMR + 2 * m + hh;
            if (r < NNODES) {
                float* src = hh ? hi : lo;
                float o[8];
                #pragma unroll
                for (int n = 0; n < 8; n++) {
                    o[n] = src[n] + bb[n];
                    if (RELU) o[n] = fmaxf(o[n], 0.f);
                }
                *(float4*)(C + (size_t)r * NC + tc * 8)     = *(float4*)&o[0];
                *(float4*)(C + (size_t)r * NC + tc * 8 + 4) = *(float4*)&o[4];
            }
        }
    }
}

// ---------------- BatchNorm (stats over g_pre) --------------------------------
__global__ void bn_stats_kernel() {
    int c = threadIdx.x;
    float s = 0.f, sq = 0.f;
    for (int r = blockIdx.x; r < NNODES; r += gridDim.x) {
        float v = g_pre[(size_t)r * DHID + c];
        s += v; sq += v * v;
    }
    atomicAdd(&g_stats[c], s);
    atomicAdd(&g_stats[DHID + c], sq);
}

__global__ void bn_finalize_kernel(const float* __restrict__ g,
                                   const float* __restrict__ be) {
    int c = threadIdx.x;
    float m = g_stats[c] / (float)NNODES;
    float v = g_stats[DHID + c] / (float)NNODES - m * m;
    float sc = g[c] * rsqrtf(v + BN_EPS);
    g_scale[c] = sc;
    g_shift[c] = be[c] - m * sc;
}

// reads g_pre, writes arg output
__global__ void bn_apply_relu_kernel(float* __restrict__ out) {
    int i = blockIdx.x * blockDim.x + threadIdx.x;   // float4 index
    if (i >= NNODES * DHID / 4) return;
    int c4 = (i % (DHID / 4)) * 4;
    float4 v  = *(const float4*)(g_pre + (size_t)i * 4);
    float4 sc = *(const float4*)(g_scale + c4);
    float4 sh = *(const float4*)(g_shift + c4);
    float4 o;
    o.x = fmaxf(v.x * sc.x + sh.x, 0.f);
    o.y = fmaxf(v.y * sc.y + sh.y, 0.f);
    o.z = fmaxf(v.z * sc.z + sh.z, 0.f);
    o.w = fmaxf(v.w * sc.w + sh.w, 0.f);
    *(float4*)(out + (size_t)i * 4) = o;
}

// ---------------- launch ------------------------------------------------------
extern "C" void kernel_launch(void* const* d_in, const int* in_sizes, int n_in,
                              void* d_out, int out_size) {
    const float* x    = (const float*)d_in[0];
    const int*   ei32 = (const int*)d_in[1];
    const float* ew   = (const float*)d_in[2];
    const float* W1   = (const float*)d_in[3];
    const float* b1   = (const float*)d_in[4];
    const float* W2   = (const float*)d_in[5];
    const float* b2   = (const float*)d_in[6];
    const float* W3   = (const float*)d_in[7];
    const float* b3   = (const float*)d_in[8];
    const float* g1   = (const float*)d_in[9];
    const float* be1  = (const float*)d_in[10];
    const float* g2   = (const float*)d_in[11];
    const float* be2  = (const float*)d_in[12];
    const float* pW1  = (const float*)d_in[13];
    const float* pb1  = (const float*)d_in[14];
    const float* pW2  = (const float*)d_in[15];
    const float* pb2  = (const float*)d_in[16];

    float* out_logits = (float*)d_out;                              // [N,64]
    float* out_h      = out_logits + (size_t)NNODES * DOUT;         // [N,128]
    float* out_z      = out_h      + (size_t)NNODES * DHID;         // [N,128]

    const int EB = (NEDGES + 255) / 256;
    const int PB = (NNODES * 32 + 255) / 256;     // warp per node
    const int GB = (NNODES + 127) / 128;
    const int AB = (NNODES * DHID / 4 + 255) / 256;

    // --- dtype detect + CSR build (parallel scan) ---
    detect_dtype_kernel<<<1, 1024>>>(ei32);
    zero_cursor_kernel<<<NB, 256>>>();
    hist_kernel<<<EB, 256>>>(ei32);
    block_reduce_kernel<<<NB, 256>>>();
    scan_bsums_kernel<<<1, 512>>>();
    block_scan_kernel<<<NB, 256>>>();
    scatter_kernel<<<EB, 256>>>(ei32, ew);

    // --- layer 1: propagate(x) @ W1.T + b1 -> bn stats ---
    propagate_kernel<false><<<PB, 256>>>(SEL_ARG, x);               // -> g_agg
    gemm_kernel<DHID, false><<<GB, 256>>>(SEL_AGG, nullptr, W1, b1,
                                          SEL_PRE, nullptr);
    zero_stats_kernel<<<1, 256>>>();
    bn_stats_kernel<<<256, DHID>>>();
    bn_finalize_kernel<<<1, DHID>>>(g1, be1);

    // --- layer 2: propagate(bn_relu(g_pre)) fused; @ W2.T + b2 -> bn ---
    propagate_kernel<true><<<PB, 256>>>(SEL_PRE, nullptr);          // -> g_agg
    gemm_kernel<DHID, false><<<GB, 256>>>(SEL_AGG, nullptr, W2, b2,
                                          SEL_PRE, nullptr);
    zero_stats_kernel<<<1, 256>>>();
    bn_stats_kernel<<<256, DHID>>>();
    bn_finalize_kernel<<<1, DHID>>>(g2, be2);
    bn_apply_relu_kernel<<<AB, 256>>>(out_h);                       // g_pre -> out_h

    // --- logits: propagate(out_h) @ W3.T + b3 -> out_logits ---
    propagate_kernel<false><<<PB, 256>>>(SEL_ARG, out_h);           // -> g_agg
    gemm_kernel<DOUT, false><<<GB, 256>>>(SEL_AGG, nullptr, W3, b3,
                                          SEL_ARG, out_logits);

    // --- proj head: z = relu(out_h @ pW1.T + pb1) @ pW2.T + pb2 -> out_z ---
    gemm_kernel<DHID, true><<<GB, 256>>>(SEL_ARG, out_h, pW1, pb1,
                                         SEL_PRE, nullptr);
    gemm_kernel<DHID, false><<<GB, 256>>>(SEL_PRE, nullptr, pW2, pb2,
                                          SEL_ARG, out_z);
}

// round 6
// speedup vs baseline: 1.1569x; 1.1569x over previous
#include <cuda_runtime.h>
#include <cuda_bf16.h>
#include <math.h>

#define NNODES 100000
#define NEDGES 1600000
#define DHID 128
#define DOUT 64
#define BN_EPS 1e-5f
#define NB ((NNODES + 255) / 256)

// buffer selectors
#define SEL_ARG 0
#define SEL_AGG 1
#define SEL_PRE 2

// ---------------- scratch (static device globals; no allocation) -------------
__device__ __align__(16) float g_agg[NNODES * DHID];
__device__ __align__(16) float g_pre[NNODES * DHID];
__device__ int   g_rowptr[NNODES + 1];
__device__ int   g_cursor[NNODES];
__device__ int   g_bsum[NB];
__device__ int   g_boff[NB];
__device__ int   g_srcs[NEDGES];
__device__ __align__(16) float g_wts [NEDGES];
__device__ float g_stats[2 * DHID];
__device__ __align__(16) float g_scale[DHID];
__device__ __align__(16) float g_shift[DHID];
__device__ __align__(16) float g_Wt[DHID * DHID];
__device__ int   g_is64;

__device__ __forceinline__ const float* sel_cbuf(int sel, const float* arg) {
    switch (sel) {
        case SEL_AGG: return g_agg;
        case SEL_PRE: return g_pre;
        default:      return arg;
    }
}
__device__ __forceinline__ float* sel_mbuf(int sel, float* arg) {
    switch (sel) {
        case SEL_AGG: return g_agg;
        case SEL_PRE: return g_pre;
        default:      return arg;
    }
}

// edge index fetch honoring runtime dtype flag (int32 vs int64 words)
__device__ __forceinline__ int fetch_src(const int* ei32, int e, int is64) {
    return is64 ? ei32[2 * e] : ei32[e];
}
__device__ __forceinline__ int fetch_dst(const int* ei32, int e, int is64) {
    return is64 ? ei32[2 * (NEDGES + e)] : ei32[NEDGES + e];
}

// ---------------- dtype detection --------------------------------------------
__global__ void detect_dtype_kernel(const int* __restrict__ ei32) {
    __shared__ int s_nonzero;
    if (threadIdx.x == 0) s_nonzero = 0;
    __syncthreads();
    for (int k = threadIdx.x; k < 4096; k += blockDim.x) {
        if (ei32[2 * k + 1] != 0) atomicOr(&s_nonzero, 1);
    }
    __syncthreads();
    if (threadIdx.x == 0) g_is64 = s_nonzero ? 0 : 1;
}

// ---------------- small utility kernels --------------------------------------
__global__ void zero_cursor_kernel() {
    int i = blockIdx.x * blockDim.x + threadIdx.x;
    if (i < NNODES) g_cursor[i] = 0;
}
__global__ void zero_stats_kernel() {
    int i = threadIdx.x;
    if (i < 2 * DHID) g_stats[i] = 0.0f;
}

// ---------------- CSR build ---------------------------------------------------
__global__ void hist_kernel(const int* __restrict__ ei32) {
    int e = blockIdx.x * blockDim.x + threadIdx.x;
    if (e < NEDGES) {
        int d = fetch_dst(ei32, e, g_is64);
        atomicAdd(&g_cursor[d], 1);
    }
}

// parallel scan stage 1: per-block sums of counts
__global__ void block_reduce_kernel() {
    __shared__ int ws[8];
    int tid = threadIdx.x, lane = tid & 31, wid = tid >> 5;
    int i = blockIdx.x * 256 + tid;
    int v = (i < NNODES) ? g_cursor[i] : 0;
    #pragma unroll
    for (int d = 16; d > 0; d >>= 1) v += __shfl_down_sync(0xFFFFFFFFu, v, d);
    if (lane == 0) ws[wid] = v;
    __syncthreads();
    if (wid == 0) {
        int s = (lane < 8) ? ws[lane] : 0;
        #pragma unroll
        for (int d = 4; d > 0; d >>= 1) s += __shfl_down_sync(0xFFFFFFFFu, s, d);
        if (lane == 0) g_bsum[blockIdx.x] = s;
    }
}

// stage 2: exclusive scan of NB block sums (single block, 512 threads)
__global__ void scan_bsums_kernel() {
    __shared__ int wsum[16];
    int tid = threadIdx.x, lane = tid & 31, wid = tid >> 5;
    int v = (tid < NB) ? g_bsum[tid] : 0;
    int x = v;
    #pragma unroll
    for (int d = 1; d < 32; d <<= 1) {
        int y = __shfl_up_sync(0xFFFFFFFFu, x, d);
        if (lane >= d) x += y;
    }
    if (lane == 31) wsum[wid] = x;
    __syncthreads();
    if (wid == 0) {
        int s = (lane < 16) ? wsum[lane] : 0;
        #pragma unroll
        for (int d = 1; d < 16; d <<= 1) {
            int y = __shfl_up_sync(0xFFFFFFFFu, s, d);
            if (lane >= d) s += y;
        }
        if (lane < 16) wsum[lane] = s;
    }
    __syncthreads();
    int incl = x + (wid > 0 ? wsum[wid - 1] : 0);
    if (tid < NB) g_boff[tid] = incl - v;
    if (tid == NB - 1) g_rowptr[NNODES] = incl;
}

// stage 3: intra-block exclusive scan + block offset -> rowptr + cursor
__global__ void block_scan_kernel() {
    __shared__ int ws[8];
    int tid = threadIdx.x, lane = tid & 31, wid = tid >> 5;
    int i = blockIdx.x * 256 + tid;
    int v = (i < NNODES) ? g_cursor[i] : 0;
    int x = v;
    #pragma unroll
    for (int d = 1; d < 32; d <<= 1) {
        int y = __shfl_up_sync(0xFFFFFFFFu, x, d);
        if (lane >= d) x += y;
    }
    if (lane == 31) ws[wid] = x;
    __syncthreads();
    if (wid == 0 && lane < 8) {
        int s = ws[lane];
        #pragma unroll
        for (int d = 1; d < 8; d <<= 1) {
            int y = __shfl_up_sync(0x000000FFu, s, d);
            if (lane >= d) s += y;
        }
        ws[lane] = s;
    }
    __syncthreads();
    int excl = x - v + (wid > 0 ? ws[wid - 1] : 0) + g_boff[blockIdx.x];
    if (i < NNODES) { g_rowptr[i] = excl; g_cursor[i] = excl; }
}

__global__ void scatter_kernel(const int* __restrict__ ei32,
                               const float* __restrict__ ew) {
    int e = blockIdx.x * blockDim.x + threadIdx.x;
    if (e < NEDGES) {
        int is64 = g_is64;
        int s = fetch_src(ei32, e, is64);
        int d = fetch_dst(ei32, e, is64);
        float w = ew[e];
        int pos = atomicAdd(&g_cursor[d], 1);
        g_srcs[pos] = s;
        g_wts [pos] = w;
    }
}

// ---------------- propagate: warp-per-node CSR gather-reduce -> g_agg ---------
// BN=true: source is g_pre with scale/shift/relu applied on the fly.
template <bool BN>
__global__ void propagate_kernel(int hsel, const float* __restrict__ harg) {
    const float* __restrict__ h = BN ? g_pre : sel_cbuf(hsel, harg);
    int warp = (blockIdx.x * blockDim.x + threadIdx.x) >> 5;
    int lane = threadIdx.x & 31;
    if (warp >= NNODES) return;
    float4 sc, sh;
    if (BN) {
        sc = ((const float4*)g_scale)[lane];
        sh = ((const float4*)g_shift)[lane];
    }
    int beg = g_rowptr[warp];
    int end = g_rowptr[warp + 1];
    float4 acc = make_float4(0.f, 0.f, 0.f, 0.f);
    for (int e = beg; e < end; e++) {
        int   s = g_srcs[e];
        float w = g_wts[e];
        float4 v = *((const float4*)(h + (size_t)s * DHID) + lane);
        if (BN) {
            v.x = fmaxf(v.x * sc.x + sh.x, 0.f);
            v.y = fmaxf(v.y * sc.y + sh.y, 0.f);
            v.z = fmaxf(v.z * sc.z + sh.z, 0.f);
            v.w = fmaxf(v.w * sc.w + sh.w, 0.f);
        }
        acc.x += w * v.x; acc.y += w * v.y;
        acc.z += w * v.z; acc.w += w * v.w;
    }
    ((float4*)(g_agg + (size_t)warp * DHID))[lane] = acc;
}

// ---------------- weight transpose: W[NC][128] -> g_Wt[128][NC] ---------------
__global__ void transpose_w_kernel(const float* __restrict__ W, int nc) {
    int idx = blockIdx.x * blockDim.x + threadIdx.x;
    if (idx < nc * DHID) {
        int o = idx / DHID, k = idx % DHID;
        g_Wt[k * nc + o] = W[idx];
    }
}

// ---------------- register-tiled fp32 GEMM (R4-proven): ----------------------
// C[N,NC] = A[N,128] @ g_Wt + bias
template <int NC, bool RELU>
__global__ void gemm_bias_kernel(int asel, const float* __restrict__ Aarg,
                                 const float* __restrict__ bias,
                                 int csel, float* __restrict__ Carg) {
    const float* __restrict__ A = sel_cbuf(asel, Aarg);
    float* __restrict__ C = sel_mbuf(csel, Carg);
    constexpr int K = 128, BK = 32, BM = 64;
    constexpr int TCOLS = NC / 4;
    constexpr int TROWS = 256 / TCOLS;
    constexpr int TM = BM / TROWS;
    __shared__ float As[BM][BK];
    __shared__ float Ws[BK][NC];

    int tid  = threadIdx.x;
    int trow = tid / TCOLS, tcol = tid % TCOLS;
    int row0 = blockIdx.x * BM;

    float acc[TM][4];
    #pragma unroll
    for (int m = 0; m < TM; m++) { acc[m][0]=acc[m][1]=acc[m][2]=acc[m][3]=0.f; }

    for (int k0 = 0; k0 < K; k0 += BK) {
        #pragma unroll
        for (int i = 0; i < (BM * BK / 4) / 256; i++) {
            int slot = tid + i * 256;
            int r = slot / (BK / 4), c4 = slot % (BK / 4);
            int gr = row0 + r;
            float4 v = (gr < NNODES)
                ? *(const float4*)(A + (size_t)gr * K + k0 + c4 * 4)
                : make_float4(0.f, 0.f, 0.f, 0.f);
            *(float4*)&As[r][c4 * 4] = v;
        }
        #pragma unroll
        for (int i = 0; i < (BK * NC / 4) / 256; i++) {
            int slot = tid + i * 256;
            int r = slot / (NC / 4), c4 = slot % (NC / 4);
            *(float4*)&Ws[r][c4 * 4] =
                *(const float4*)(g_Wt + (size_t)(k0 + r) * NC + c4 * 4);
        }
        __syncthreads();
        #pragma unroll
        for (int kk = 0; kk < BK; kk++) {
            float4 w = *(float4*)&Ws[kk][tcol * 4];
            #pragma unroll
            for (int m = 0; m < TM; m++) {
                float a = As[trow * TM + m][kk];
                acc[m][0] += a * w.x; acc[m][1] += a * w.y;
                acc[m][2] += a * w.z; acc[m][3] += a * w.w;
            }
        }
        __syncthreads();
    }

    float4 b = *(const float4*)(bias + tcol * 4);
    #pragma unroll
    for (int m = 0; m < TM; m++) {
        int gr = row0 + trow * TM + m;
        if (gr < NNODES) {
            float4 o;
            o.x = acc[m][0] + b.x; o.y = acc[m][1] + b.y;
            o.z = acc[m][2] + b.z; o.w = acc[m][3] + b.w;
            if (RELU) {
                o.x = fmaxf(o.x, 0.f); o.y = fmaxf(o.y, 0.f);
                o.z = fmaxf(o.z, 0.f); o.w = fmaxf(o.w, 0.f);
            }
            *(float4*)(C + (size_t)gr * NC + tcol * 4) = o;
        }
    }
}

// ---------------- BatchNorm (stats over g_pre) --------------------------------
__global__ void bn_stats_kernel() {
    int c = threadIdx.x;
    float s = 0.f, sq = 0.f;
    for (int r = blockIdx.x; r < NNODES; r += gridDim.x) {
        float v = g_pre[(size_t)r * DHID + c];
        s += v; sq += v * v;
    }
    atomicAdd(&g_stats[c], s);
    atomicAdd(&g_stats[DHID + c], sq);
}

__global__ void bn_finalize_kernel(const float* __restrict__ g,
                                   const float* __restrict__ be) {
    int c = threadIdx.x;
    float m = g_stats[c] / (float)NNODES;
    float v = g_stats[DHID + c] / (float)NNODES - m * m;
    float sc = g[c] * rsqrtf(v + BN_EPS);
    g_scale[c] = sc;
    g_shift[c] = be[c] - m * sc;
}

// reads g_pre, writes arg output
__global__ void bn_apply_relu_kernel(float* __restrict__ out) {
    int i = blockIdx.x * blockDim.x + threadIdx.x;   // float4 index
    if (i >= NNODES * DHID / 4) return;
    int c4 = (i % (DHID / 4)) * 4;
    float4 v  = *(const float4*)(g_pre + (size_t)i * 4);
    float4 sc = *(const float4*)(g_scale + c4);
    float4 sh = *(const float4*)(g_shift + c4);
    float4 o;
    o.x = fmaxf(v.x * sc.x + sh.x, 0.f);
    o.y = fmaxf(v.y * sc.y + sh.y, 0.f);
    o.z = fmaxf(v.z * sc.z + sh.z, 0.f);
    o.w = fmaxf(v.w * sc.w + sh.w, 0.f);
    *(float4*)(out + (size_t)i * 4) = o;
}

// ---------------- launch ------------------------------------------------------
extern "C" void kernel_launch(void* const* d_in, const int* in_sizes, int n_in,
                              void* d_out, int out_size) {
    const float* x    = (const float*)d_in[0];
    const int*   ei32 = (const int*)d_in[1];
    const float* ew   = (const float*)d_in[2];
    const float* W1   = (const float*)d_in[3];
    const float* b1   = (const float*)d_in[4];
    const float* W2   = (const float*)d_in[5];
    const float* b2   = (const float*)d_in[6];
    const float* W3   = (const float*)d_in[7];
    const float* b3   = (const float*)d_in[8];
    const float* g1   = (const float*)d_in[9];
    const float* be1  = (const float*)d_in[10];
    const float* g2   = (const float*)d_in[11];
    const float* be2  = (const float*)d_in[12];
    const float* pW1  = (const float*)d_in[13];
    const float* pb1  = (const float*)d_in[14];
    const float* pW2  = (const float*)d_in[15];
    const float* pb2  = (const float*)d_in[16];

    float* out_logits = (float*)d_out;                              // [N,64]
    float* out_h      = out_logits + (size_t)NNODES * DOUT;         // [N,128]
    float* out_z      = out_h      + (size_t)NNODES * DHID;         // [N,128]

    const int EB = (NEDGES + 255) / 256;
    const int PB = (NNODES * 32 + 255) / 256;     // warp per node
    const int GB = (NNODES + 63) / 64;
    const int AB = (NNODES * DHID / 4 + 255) / 256;

    // --- dtype detect + CSR build (parallel scan) ---
    detect_dtype_kernel<<<1, 1024>>>(ei32);
    zero_cursor_kernel<<<NB, 256>>>();
    hist_kernel<<<EB, 256>>>(ei32);
    block_reduce_kernel<<<NB, 256>>>();
    scan_bsums_kernel<<<1, 512>>>();
    block_scan_kernel<<<NB, 256>>>();
    scatter_kernel<<<EB, 256>>>(ei32, ew);

    // --- layer 1: propagate(x) @ W1.T + b1 -> bn stats ---
    propagate_kernel<false><<<PB, 256>>>(SEL_ARG, x);               // -> g_agg
    transpose_w_kernel<<<(DHID * DHID + 255) / 256, 256>>>(W1, DHID);
    gemm_bias_kernel<DHID, false><<<GB, 256>>>(SEL_AGG, nullptr, b1,
                                               SEL_PRE, nullptr);
    zero_stats_kernel<<<1, 256>>>();
    bn_stats_kernel<<<256, DHID>>>();
    bn_finalize_kernel<<<1, DHID>>>(g1, be1);

    // --- layer 2: propagate(bn_relu(g_pre)) fused -> gemm -> bn ---
    propagate_kernel<true><<<PB, 256>>>(SEL_PRE, nullptr);          // -> g_agg
    transpose_w_kernel<<<(DHID * DHID + 255) / 256, 256>>>(W2, DHID);
    gemm_bias_kernel<DHID, false><<<GB, 256>>>(SEL_AGG, nullptr, b2,
                                               SEL_PRE, nullptr);
    zero_stats_kernel<<<1, 256>>>();
    bn_stats_kernel<<<256, DHID>>>();
    bn_finalize_kernel<<<1, DHID>>>(g2, be2);
    bn_apply_relu_kernel<<<AB, 256>>>(out_h);                       // g_pre -> out_h

    // --- logits: propagate(out_h) @ W3.T + b3 -> out_logits ---
    propagate_kernel<false><<<PB, 256>>>(SEL_ARG, out_h);           // -> g_agg
    transpose_w_kernel<<<(DOUT * DHID + 255) / 256, 256>>>(W3, DOUT);
    gemm_bias_kernel<DOUT, false><<<GB, 256>>>(SEL_AGG, nullptr, b3,
                                               SEL_ARG, out_logits);

    // --- proj head: z = relu(out_h @ pW1.T + pb1) @ pW2.T + pb2 -> out_z ---
    transpose_w_kernel<<<(DHID * DHID + 255) / 256, 256>>>(pW1, DHID);
    gemm_bias_kernel<DHID, true><<<GB, 256>>>(SEL_ARG, out_h, pb1,
                                              SEL_PRE, nullptr);
    transpose_w_kernel<<<(DHID * DHID + 255) / 256, 256>>>(pW2, DHID);
    gemm_bias_kernel<DHID, false><<<GB, 256>>>(SEL_PRE, nullptr, pb2,
                                               SEL_ARG, out_z);
}